// round 8
// baseline (speedup 1.0000x reference)
#include <cuda_runtime.h>
#include <stdint.h>

#define NB   16
#define NP   2000
#define NG   100
#define IH   160
#define IW   160
#define MHH  28
#define MWW  28
#define NPOS 66
#define NNEG 134
#define TR   200

#define ROIS_OFF 0
#define CLS_OFF  (NB*TR*4)            /* 12800 */
#define DLT_OFF  (CLS_OFF + NB*TR)    /* 16000 */
#define MSK_OFF  (DLT_OFF + NB*TR*4)  /* 28800 */

__device__ float g_pbox[NB*NPOS*4];
__device__ int   g_gidx[NB*NPOS];
__device__ int   g_pval[NB*NPOS];

// ---------------- Threefry-2x32 ----------------
__device__ __forceinline__ void tf(uint32_t k0, uint32_t k1, uint32_t& x0, uint32_t& x1) {
    uint32_t k2 = k0 ^ k1 ^ 0x1BD11BDAu;
    x0 += k0; x1 += k1;
#define RND(r) { x0 += x1; x1 = (x1 << (r)) | (x1 >> (32 - (r))); x1 ^= x0; }
    RND(13) RND(15) RND(26) RND(6)
    x0 += k1; x1 += k2 + 1u;
    RND(17) RND(29) RND(16) RND(24)
    x0 += k2; x1 += k0 + 2u;
    RND(13) RND(15) RND(26) RND(6)
    x0 += k0; x1 += k1 + 3u;
    RND(17) RND(29) RND(16) RND(24)
    x0 += k1; x1 += k2 + 4u;
    RND(13) RND(15) RND(26) RND(6)
    x0 += k2; x1 += k0 + 5u;
#undef RND
}

// jax.random.uniform(key,(2000,)) element p — threefry_partitionable=True path:
// bits[p] = w0 ^ w1 of TF(key, (0, p)); float in [0,1) via mantissa trick.
__device__ __forceinline__ float jax_unif(uint32_t k0, uint32_t k1, int p) {
    uint32_t x0 = 0u, x1 = (uint32_t)p;
    tf(k0, k1, x0, x1);
    uint32_t bits = x0 ^ x1;
    float f = __uint_as_float((bits >> 9) | 0x3F800000u) - 1.0f;
    return fmaxf(0.0f, f);
}

// ---------------- IoU (unfused rounding to match XLA elementwise) ----------
__device__ __forceinline__ float iou_f(float4 p, float4 g) {
    float yA = fmaxf(p.x, g.x), xA = fmaxf(p.y, g.y);
    float yB = fminf(p.z, g.z), xB = fminf(p.w, g.w);
    float ih = fmaxf(__fsub_rn(yB, yA), 0.0f);
    float iw = fmaxf(__fsub_rn(xB, xA), 0.0f);
    float inter = __fmul_rn(ih, iw);
    float a1 = __fmul_rn(__fsub_rn(p.z, p.x), __fsub_rn(p.w, p.y));
    float a2 = __fmul_rn(__fsub_rn(g.z, g.x), __fsub_rn(g.w, g.y));
    float uni = __fsub_rn(__fadd_rn(a1, a2), inter);
    return __fdiv_rn(inter, fmaxf(uni, 1e-10f));
}

// ---------------- Kernel A: per-image scoring, top-k selection, rois/deltas --
__global__ __launch_bounds__(256) void kA(const float* __restrict__ prop,
                                          const int*   __restrict__ gcls,
                                          const float* __restrict__ gbox,
                                          const float* __restrict__ stdv,
                                          float* __restrict__ out) {
    const int b = blockIdx.x;
    const int tid = threadIdx.x;

    __shared__ float4 s_gt[NG];
    __shared__ int    s_gtv[NG];
    __shared__ float  s_sp[NP];
    __shared__ float  s_sn[NP];
    __shared__ float  s_rv[256];
    __shared__ int    s_ri[256];
    __shared__ int    s_pidx[NPOS];
    __shared__ int    s_pvalid[NPOS];
    __shared__ int    s_nidx[NNEG];
    __shared__ int    s_nvalid[NNEG];
    __shared__ int    s_nn;
    __shared__ uint32_t s_keys[4];

    for (int g = tid; g < NG; g += 256) {
        const float* gp = gbox + ((size_t)b * NG + g) * 4;
        s_gt[g] = make_float4(gp[0], gp[1], gp[2], gp[3]);
        s_gtv[g] = (gcls[b * NG + g] > 0) ? 1 : 0;
    }
    if (tid == 0) {
        // threefry_partitionable=True key derivation:
        // keys[b] = TF((0,42),(0,b));  kp = TF(keys[b],(0,0));  kn = TF(keys[b],(0,1))
        uint32_t kb0 = 0u, kb1 = (uint32_t)b;
        tf(0u, 42u, kb0, kb1);
        uint32_t p0 = 0u, p1 = 0u; tf(kb0, kb1, p0, p1);
        uint32_t n0 = 0u, n1 = 1u; tf(kb0, kb1, n0, n1);
        s_keys[0] = p0; s_keys[1] = p1;   // kp
        s_keys[2] = n0; s_keys[3] = n1;   // kn
    }
    __syncthreads();
    const uint32_t kp0 = s_keys[0], kp1 = s_keys[1];
    const uint32_t kn0 = s_keys[2], kn1 = s_keys[3];

    const float4* pb4 = (const float4*)(prop + (size_t)b * NP * 4);

    // scores
    for (int p = tid; p < NP; p += 256) {
        float4 pb = pb4[p];
        bool vp = (pb.x != 0.0f) || (pb.y != 0.0f) || (pb.z != 0.0f) || (pb.w != 0.0f);
        float m = -1.0f;
        #pragma unroll 4
        for (int g = 0; g < NG; g++) {
            float v = s_gtv[g] ? iou_f(pb, s_gt[g]) : -1.0f;
            m = fmaxf(m, v);
        }
        bool pos = (m >= 0.5f) && vp;
        bool neg = (m <  0.5f) && vp;
        s_sp[p] = pos ? jax_unif(kp0, kp1, p) : -1.0f;
        s_sn[p] = neg ? jax_unif(kn0, kn1, p) : -1.0f;
    }
    __syncthreads();

    // top-NPOS over s_sp (lax.top_k tie-break: lowest index first)
    for (int it = 0; it < NPOS; it++) {
        float bv = -1e30f; int bi = NP;
        for (int p = tid; p < NP; p += 256) {
            float v = s_sp[p];
            if (v > bv) { bv = v; bi = p; }
        }
        s_rv[tid] = bv; s_ri[tid] = bi;
        __syncthreads();
        for (int s = 128; s > 0; s >>= 1) {
            if (tid < s) {
                float ov = s_rv[tid + s]; int oi = s_ri[tid + s];
                if (ov > s_rv[tid] || (ov == s_rv[tid] && oi < s_ri[tid])) {
                    s_rv[tid] = ov; s_ri[tid] = oi;
                }
            }
            __syncthreads();
        }
        if (tid == 0) {
            int idx = s_ri[0];
            s_pidx[it] = idx;
            s_pvalid[it] = (s_rv[0] > 0.0f) ? 1 : 0;
            s_sp[idx] = -3.0f;
        }
        __syncthreads();
    }

    if (tid == 0) {
        int P = 0;
        for (int i = 0; i < NPOS; i++) P += s_pvalid[i];
        // XLA lowers x/0.33f to x * (1/0.33f): at P=66 this gives 200.0 (not
        // the correctly-rounded 199.99998474 of div.rn) -> nn = 134.
        constexpr float RCP33 = 1.0f / 0.33f;
        int nn = (int)(__fmul_rn((float)P, RCP33)) - P;
        nn = max(0, min(nn, NNEG));
        s_nn = nn;
    }
    __syncthreads();

    // top-NNEG over s_sn
    for (int it = 0; it < NNEG; it++) {
        float bv = -1e30f; int bi = NP;
        for (int p = tid; p < NP; p += 256) {
            float v = s_sn[p];
            if (v > bv) { bv = v; bi = p; }
        }
        s_rv[tid] = bv; s_ri[tid] = bi;
        __syncthreads();
        for (int s = 128; s > 0; s >>= 1) {
            if (tid < s) {
                float ov = s_rv[tid + s]; int oi = s_ri[tid + s];
                if (ov > s_rv[tid] || (ov == s_rv[tid] && oi < s_ri[tid])) {
                    s_rv[tid] = ov; s_ri[tid] = oi;
                }
            }
            __syncthreads();
        }
        if (tid == 0) {
            int idx = s_ri[0];
            s_nidx[it] = idx;
            s_nvalid[it] = (s_rv[0] > 0.0f) ? 1 : 0;
            s_sn[idx] = -3.0f;
        }
        __syncthreads();
    }

    const float sd0 = stdv[0], sd1 = stdv[1], sd2 = stdv[2], sd3 = stdv[3];

    // positive slots: class/deltas/rois + scratch for mask kernel
    for (int i = tid; i < NPOS; i += 256) {
        int idx = s_pidx[i];
        int valid = s_pvalid[i];
        float4 pb = pb4[idx];

        // argmax over masked overlaps (first max on ties)
        float bv = -2.0f; int bg = 0;
        for (int g = 0; g < NG; g++) {
            float v = s_gtv[g] ? iou_f(pb, s_gt[g]) : -1.0f;
            if (v > bv) { bv = v; bg = g; }
        }
        float4 gb = valid ? s_gt[bg] : pb;
        int cls = valid ? gcls[b * NG + bg] : 0;

        float h  = __fsub_rn(pb.z, pb.x), w  = __fsub_rn(pb.w, pb.y);
        float cy = __fadd_rn(pb.x, __fmul_rn(0.5f, h));
        float cx = __fadd_rn(pb.y, __fmul_rn(0.5f, w));
        float gh  = __fsub_rn(gb.z, gb.x), gw  = __fsub_rn(gb.w, gb.y);
        float gcy = __fadd_rn(gb.x, __fmul_rn(0.5f, gh));
        float gcx = __fadd_rn(gb.y, __fmul_rn(0.5f, gw));
        float d0 = __fdiv_rn(__fdiv_rn(__fsub_rn(gcy, cy), h), sd0);
        float d1 = __fdiv_rn(__fdiv_rn(__fsub_rn(gcx, cx), w), sd1);
        float d2 = __fdiv_rn(logf(__fdiv_rn(gh, h)), sd2);
        float d3 = __fdiv_rn(logf(__fdiv_rn(gw, w)), sd3);

        float fv = valid ? 1.0f : 0.0f;
        size_t ro = (size_t)ROIS_OFF + ((size_t)b * TR + i) * 4;
        out[ro + 0] = __fmul_rn(pb.x, fv);
        out[ro + 1] = __fmul_rn(pb.y, fv);
        out[ro + 2] = __fmul_rn(pb.z, fv);
        out[ro + 3] = __fmul_rn(pb.w, fv);
        out[CLS_OFF + (size_t)b * TR + i] = (float)cls;   // output packed as f32
        size_t dofs = (size_t)DLT_OFF + ((size_t)b * TR + i) * 4;
        out[dofs + 0] = __fmul_rn(d0, fv);
        out[dofs + 1] = __fmul_rn(d1, fv);
        out[dofs + 2] = __fmul_rn(d2, fv);
        out[dofs + 3] = __fmul_rn(d3, fv);

        int si = b * NPOS + i;
        g_pbox[si * 4 + 0] = pb.x; g_pbox[si * 4 + 1] = pb.y;
        g_pbox[si * 4 + 2] = pb.z; g_pbox[si * 4 + 3] = pb.w;
        g_gidx[si] = bg;
        g_pval[si] = valid;
    }

    // negative slots
    for (int j = tid; j < NNEG; j += 256) {
        int slot = NPOS + j;
        int idx = s_nidx[j];
        float nv = (s_nvalid[j] && (j < s_nn)) ? 1.0f : 0.0f;
        float4 pb = pb4[idx];
        size_t ro = (size_t)ROIS_OFF + ((size_t)b * TR + slot) * 4;
        out[ro + 0] = __fmul_rn(pb.x, nv);
        out[ro + 1] = __fmul_rn(pb.y, nv);
        out[ro + 2] = __fmul_rn(pb.z, nv);
        out[ro + 3] = __fmul_rn(pb.w, nv);
        out[CLS_OFF + (size_t)b * TR + slot] = 0.0f;
        size_t dofs = (size_t)DLT_OFF + ((size_t)b * TR + slot) * 4;
        out[dofs + 0] = 0.0f; out[dofs + 1] = 0.0f;
        out[dofs + 2] = 0.0f; out[dofs + 3] = 0.0f;
    }
}

// ---------------- Kernel B: mask crop_and_resize + round --------------------
__global__ __launch_bounds__(128) void kB(const float* __restrict__ pmasks,
                                          float* __restrict__ out) {
    const int slot = blockIdx.x;
    const int b = blockIdx.y;
    float* o = out + (size_t)MSK_OFF + ((size_t)b * TR + slot) * (MHH * MWW);

    if (slot >= NPOS || !g_pval[b * NPOS + slot]) {
        for (int px = threadIdx.x; px < MHH * MWW; px += 128) o[px] = 0.0f;
        return;
    }
    const int si = b * NPOS + slot;
    const float y1 = g_pbox[si * 4 + 0], x1 = g_pbox[si * 4 + 1];
    const float y2 = g_pbox[si * 4 + 2], x2 = g_pbox[si * 4 + 3];
    const int g = g_gidx[si];
    const float* img = pmasks + (size_t)b * (IH * IW * NG) + g;
    const float dy = __fsub_rn(y2, y1), dx = __fsub_rn(x2, x1);

    for (int px = threadIdx.x; px < MHH * MWW; px += 128) {
        int i = px / MWW, j = px - i * MWW;
        float ty = __fdiv_rn((float)i, 27.0f);
        float tx = __fdiv_rn((float)j, 27.0f);
        float ys = __fmul_rn(__fadd_rn(y1, __fmul_rn(ty, dy)), 159.0f);
        float xs = __fmul_rn(__fadd_rn(x1, __fmul_rn(tx, dx)), 159.0f);
        float y0f = floorf(ys), x0f = floorf(xs);
        float fy = __fsub_rn(ys, y0f), fx = __fsub_rn(xs, x0f);
        int y0 = min(max((int)y0f, 0), IH - 1);
        int x0 = min(max((int)x0f, 0), IW - 1);
        int y1i = min(y0 + 1, IH - 1);
        int x1i = min(x0 + 1, IW - 1);
        float m00 = img[((size_t)y0 * IW + x0) * NG];
        float m01 = img[((size_t)y0 * IW + x1i) * NG];
        float m10 = img[((size_t)y1i * IW + x0) * NG];
        float m11 = img[((size_t)y1i * IW + x1i) * NG];
        float ofy = __fsub_rn(1.0f, fy), ofx = __fsub_rn(1.0f, fx);
        float v = __fadd_rn(__fadd_rn(__fadd_rn(
                    __fmul_rn(__fmul_rn(m00, ofy), ofx),
                    __fmul_rn(__fmul_rn(m01, ofy), fx)),
                    __fmul_rn(__fmul_rn(m10, fy), ofx)),
                    __fmul_rn(__fmul_rn(m11, fy), fx));
        o[px] = rintf(v);
    }
}

extern "C" void kernel_launch(void* const* d_in, const int* in_sizes, int n_in,
                              void* d_out, int out_size) {
    const float* prop   = (const float*)d_in[0];
    const int*   gcls   = (const int*)d_in[1];
    const float* gbox   = (const float*)d_in[2];
    const float* pmasks = (const float*)d_in[3];
    const float* stdv   = (const float*)d_in[4];
    float* out = (float*)d_out;

    kA<<<NB, 256>>>(prop, gcls, gbox, stdv, out);
    kB<<<dim3(TR, NB), 128>>>(pmasks, out);
}

// round 9
// speedup vs baseline: 1.4813x; 1.4813x over previous
#include <cuda_runtime.h>
#include <stdint.h>

#define NB   16
#define NP   2000
#define NSORT 2048
#define NG   100
#define IH   160
#define IW   160
#define MHH  28
#define MWW  28
#define NPOS 66
#define NNEG 134
#define TR   200

#define ROIS_OFF 0
#define CLS_OFF  (NB*TR*4)            /* 12800 */
#define DLT_OFF  (CLS_OFF + NB*TR)    /* 16000 */
#define MSK_OFF  (DLT_OFF + NB*TR*4)  /* 28800 */

__device__ float g_pbox[NB*NPOS*4];
__device__ int   g_gidx[NB*NPOS];
__device__ int   g_pval[NB*NPOS];

// ---------------- Threefry-2x32 ----------------
__device__ __forceinline__ void tf(uint32_t k0, uint32_t k1, uint32_t& x0, uint32_t& x1) {
    uint32_t k2 = k0 ^ k1 ^ 0x1BD11BDAu;
    x0 += k0; x1 += k1;
#define RND(r) { x0 += x1; x1 = (x1 << (r)) | (x1 >> (32 - (r))); x1 ^= x0; }
    RND(13) RND(15) RND(26) RND(6)
    x0 += k1; x1 += k2 + 1u;
    RND(17) RND(29) RND(16) RND(24)
    x0 += k2; x1 += k0 + 2u;
    RND(13) RND(15) RND(26) RND(6)
    x0 += k0; x1 += k1 + 3u;
    RND(17) RND(29) RND(16) RND(24)
    x0 += k1; x1 += k2 + 4u;
    RND(13) RND(15) RND(26) RND(6)
    x0 += k2; x1 += k0 + 5u;
#undef RND
}

// jax.random.uniform(key,(2000,)) element p — threefry_partitionable=True path.
__device__ __forceinline__ float jax_unif(uint32_t k0, uint32_t k1, int p) {
    uint32_t x0 = 0u, x1 = (uint32_t)p;
    tf(k0, k1, x0, x1);
    uint32_t bits = x0 ^ x1;
    float f = __uint_as_float((bits >> 9) | 0x3F800000u) - 1.0f;
    return fmaxf(0.0f, f);
}

// Order-preserving float->uint32 map (total order, ascending).
__device__ __forceinline__ uint32_t ford(float f) {
    uint32_t b = __float_as_uint(f);
    return (b & 0x80000000u) ? ~b : (b | 0x80000000u);
}

// ---------------- IoU (unfused rounding to match XLA elementwise) ----------
__device__ __forceinline__ float iou_f(float4 p, float4 g) {
    float yA = fmaxf(p.x, g.x), xA = fmaxf(p.y, g.y);
    float yB = fminf(p.z, g.z), xB = fminf(p.w, g.w);
    float ih = fmaxf(__fsub_rn(yB, yA), 0.0f);
    float iw = fmaxf(__fsub_rn(xB, xA), 0.0f);
    float inter = __fmul_rn(ih, iw);
    float a1 = __fmul_rn(__fsub_rn(p.z, p.x), __fsub_rn(p.w, p.y));
    float a2 = __fmul_rn(__fsub_rn(g.z, g.x), __fsub_rn(g.w, g.y));
    float uni = __fsub_rn(__fadd_rn(a1, a2), inter);
    return __fdiv_rn(inter, fmaxf(uni, 1e-10f));
}

// ---------------- Kernel A ----------------
__global__ __launch_bounds__(256) void kA(const float* __restrict__ prop,
                                          const int*   __restrict__ gcls,
                                          const float* __restrict__ gbox,
                                          const float* __restrict__ stdv,
                                          float* __restrict__ out) {
    const int b = blockIdx.x;
    const int tid = threadIdx.x;

    __shared__ float4 s_gt[NG];
    __shared__ int    s_gtv[NG];
    __shared__ float  s_m[NP];                 // max IoU; -2.0f = invalid proposal
    __shared__ unsigned long long s_key[NSORT];
    __shared__ int    s_pidx[NPOS];
    __shared__ int    s_pvalid[NPOS];
    __shared__ int    s_nidx[NNEG];
    __shared__ int    s_nvalid[NNEG];
    __shared__ int    s_nn;
    __shared__ uint32_t s_keys[4];

    for (int g = tid; g < NG; g += 256) {
        const float* gp = gbox + ((size_t)b * NG + g) * 4;
        s_gt[g] = make_float4(gp[0], gp[1], gp[2], gp[3]);
        s_gtv[g] = (gcls[b * NG + g] > 0) ? 1 : 0;
    }
    if (tid == 0) {
        // keys[b] = TF((0,42),(0,b)); kp = TF(keys[b],(0,0)); kn = TF(keys[b],(0,1))
        uint32_t kb0 = 0u, kb1 = (uint32_t)b;
        tf(0u, 42u, kb0, kb1);
        uint32_t p0 = 0u, p1 = 0u; tf(kb0, kb1, p0, p1);
        uint32_t n0 = 0u, n1 = 1u; tf(kb0, kb1, n0, n1);
        s_keys[0] = p0; s_keys[1] = p1;   // kp
        s_keys[2] = n0; s_keys[3] = n1;   // kn
    }
    __syncthreads();
    const uint32_t kp0 = s_keys[0], kp1 = s_keys[1];
    const uint32_t kn0 = s_keys[2], kn1 = s_keys[3];

    const float4* pb4 = (const float4*)(prop + (size_t)b * NP * 4);

    // ---- scoring: max IoU per proposal ----
    for (int p = tid; p < NP; p += 256) {
        float4 pb = pb4[p];
        bool vp = (pb.x != 0.0f) || (pb.y != 0.0f) || (pb.z != 0.0f) || (pb.w != 0.0f);
        float m = -1.0f;
        #pragma unroll 4
        for (int g = 0; g < NG; g++) {
            float v = s_gtv[g] ? iou_f(pb, s_gt[g]) : -1.0f;
            m = fmaxf(m, v);
        }
        s_m[p] = vp ? m : -2.0f;
    }
    __syncthreads();

    // ---- build positive keys: (ford(score)<<32) | (NP-1-p); padding = 0 ----
    // score = uniform if positive else -1.0 (matches top_k over masked array).
    for (int i = tid; i < NSORT; i += 256) {
        unsigned long long key = 0ull;
        if (i < NP) {
            float m = s_m[i];
            bool pos = (m >= 0.5f);            // m=-2 (invalid) can't pass
            float sc = pos ? jax_unif(kp0, kp1, i) : -1.0f;
            key = ((unsigned long long)ford(sc) << 32) | (uint32_t)(NP - 1 - i);
        }
        s_key[i] = key;
    }

    // ---- bitonic sort, descending (exactly reproduces lax.top_k order) ----
    for (unsigned k = 2; k <= NSORT; k <<= 1) {
        for (unsigned j = k >> 1; j > 0; j >>= 1) {
            __syncthreads();
            for (unsigned i = tid; i < NSORT; i += 256) {
                unsigned ixj = i ^ j;
                if (ixj > i) {
                    unsigned long long a = s_key[i], c = s_key[ixj];
                    bool up = ((i & k) == 0);
                    if (up ? (a < c) : (a > c)) { s_key[i] = c; s_key[ixj] = a; }
                }
            }
        }
    }
    __syncthreads();

    // ---- extract top-NPOS ----
    if (tid < NPOS) {
        unsigned long long key = s_key[tid];
        uint32_t u = (uint32_t)(key >> 32);
        s_pvalid[tid] = (u > 0x80000000u) ? 1 : 0;     // score > 0.0
        s_pidx[tid]   = NP - 1 - (int)(key & 0xFFFFFFFFu);
    }
    __syncthreads();

    if (tid == 0) {
        int P = 0;
        for (int i = 0; i < NPOS; i++) P += s_pvalid[i];
        // XLA lowers x/0.33f to x * (1/0.33f): P=66 -> 200.0 -> nn=134.
        constexpr float RCP33 = 1.0f / 0.33f;
        int nn = (int)(__fmul_rn((float)P, RCP33)) - P;
        nn = max(0, min(nn, NNEG));
        s_nn = nn;
    }
    __syncthreads();

    // ---- build negative keys and sort ----
    for (int i = tid; i < NSORT; i += 256) {
        unsigned long long key = 0ull;
        if (i < NP) {
            float m = s_m[i];
            bool neg = (m < 0.5f) && (m > -1.5f);      // valid proposal, IoU<0.5
            float sc = neg ? jax_unif(kn0, kn1, i) : -1.0f;
            key = ((unsigned long long)ford(sc) << 32) | (uint32_t)(NP - 1 - i);
        }
        s_key[i] = key;
    }
    for (unsigned k = 2; k <= NSORT; k <<= 1) {
        for (unsigned j = k >> 1; j > 0; j >>= 1) {
            __syncthreads();
            for (unsigned i = tid; i < NSORT; i += 256) {
                unsigned ixj = i ^ j;
                if (ixj > i) {
                    unsigned long long a = s_key[i], c = s_key[ixj];
                    bool up = ((i & k) == 0);
                    if (up ? (a < c) : (a > c)) { s_key[i] = c; s_key[ixj] = a; }
                }
            }
        }
    }
    __syncthreads();
    if (tid < NNEG) {
        unsigned long long key = s_key[tid];
        uint32_t u = (uint32_t)(key >> 32);
        s_nvalid[tid] = (u > 0x80000000u) ? 1 : 0;
        s_nidx[tid]   = NP - 1 - (int)(key & 0xFFFFFFFFu);
    }
    __syncthreads();

    const float sd0 = stdv[0], sd1 = stdv[1], sd2 = stdv[2], sd3 = stdv[3];

    // ---- positive slots: rois/class/deltas + scratch for mask kernel ----
    for (int i = tid; i < NPOS; i += 256) {
        int idx = s_pidx[i];
        int valid = s_pvalid[i];
        float4 pb = pb4[idx];

        // argmax over masked overlaps (first max on ties)
        float bv = -2.0f; int bg = 0;
        for (int g = 0; g < NG; g++) {
            float v = s_gtv[g] ? iou_f(pb, s_gt[g]) : -1.0f;
            if (v > bv) { bv = v; bg = g; }
        }
        float4 gb = valid ? s_gt[bg] : pb;
        int cls = valid ? gcls[b * NG + bg] : 0;

        float h  = __fsub_rn(pb.z, pb.x), w  = __fsub_rn(pb.w, pb.y);
        float cy = __fadd_rn(pb.x, __fmul_rn(0.5f, h));
        float cx = __fadd_rn(pb.y, __fmul_rn(0.5f, w));
        float gh  = __fsub_rn(gb.z, gb.x), gw  = __fsub_rn(gb.w, gb.y);
        float gcy = __fadd_rn(gb.x, __fmul_rn(0.5f, gh));
        float gcx = __fadd_rn(gb.y, __fmul_rn(0.5f, gw));
        float d0 = __fdiv_rn(__fdiv_rn(__fsub_rn(gcy, cy), h), sd0);
        float d1 = __fdiv_rn(__fdiv_rn(__fsub_rn(gcx, cx), w), sd1);
        float d2 = __fdiv_rn(logf(__fdiv_rn(gh, h)), sd2);
        float d3 = __fdiv_rn(logf(__fdiv_rn(gw, w)), sd3);

        float fv = valid ? 1.0f : 0.0f;
        size_t ro = (size_t)ROIS_OFF + ((size_t)b * TR + i) * 4;
        out[ro + 0] = __fmul_rn(pb.x, fv);
        out[ro + 1] = __fmul_rn(pb.y, fv);
        out[ro + 2] = __fmul_rn(pb.z, fv);
        out[ro + 3] = __fmul_rn(pb.w, fv);
        out[CLS_OFF + (size_t)b * TR + i] = (float)cls;   // output packed as f32
        size_t dofs = (size_t)DLT_OFF + ((size_t)b * TR + i) * 4;
        out[dofs + 0] = __fmul_rn(d0, fv);
        out[dofs + 1] = __fmul_rn(d1, fv);
        out[dofs + 2] = __fmul_rn(d2, fv);
        out[dofs + 3] = __fmul_rn(d3, fv);

        int si = b * NPOS + i;
        g_pbox[si * 4 + 0] = pb.x; g_pbox[si * 4 + 1] = pb.y;
        g_pbox[si * 4 + 2] = pb.z; g_pbox[si * 4 + 3] = pb.w;
        g_gidx[si] = bg;
        g_pval[si] = valid;
    }

    // ---- negative slots ----
    for (int j = tid; j < NNEG; j += 256) {
        int slot = NPOS + j;
        int idx = s_nidx[j];
        float nv = (s_nvalid[j] && (j < s_nn)) ? 1.0f : 0.0f;
        float4 pb = pb4[idx];
        size_t ro = (size_t)ROIS_OFF + ((size_t)b * TR + slot) * 4;
        out[ro + 0] = __fmul_rn(pb.x, nv);
        out[ro + 1] = __fmul_rn(pb.y, nv);
        out[ro + 2] = __fmul_rn(pb.z, nv);
        out[ro + 3] = __fmul_rn(pb.w, nv);
        out[CLS_OFF + (size_t)b * TR + slot] = 0.0f;
        size_t dofs = (size_t)DLT_OFF + ((size_t)b * TR + slot) * 4;
        out[dofs + 0] = 0.0f; out[dofs + 1] = 0.0f;
        out[dofs + 2] = 0.0f; out[dofs + 3] = 0.0f;
    }
}

// ---------------- Kernel B: mask crop_and_resize + round --------------------
__global__ __launch_bounds__(128) void kB(const float* __restrict__ pmasks,
                                          float* __restrict__ out) {
    const int slot = blockIdx.x;
    const int b = blockIdx.y;
    float* o = out + (size_t)MSK_OFF + ((size_t)b * TR + slot) * (MHH * MWW);

    if (slot >= NPOS || !g_pval[b * NPOS + slot]) {
        for (int px = threadIdx.x; px < MHH * MWW; px += 128) o[px] = 0.0f;
        return;
    }
    const int si = b * NPOS + slot;
    const float y1 = g_pbox[si * 4 + 0], x1 = g_pbox[si * 4 + 1];
    const float y2 = g_pbox[si * 4 + 2], x2 = g_pbox[si * 4 + 3];
    const int g = g_gidx[si];
    const float* img = pmasks + (size_t)b * (IH * IW * NG) + g;
    const float dy = __fsub_rn(y2, y1), dx = __fsub_rn(x2, x1);

    for (int px = threadIdx.x; px < MHH * MWW; px += 128) {
        int i = px / MWW, j = px - i * MWW;
        float ty = __fdiv_rn((float)i, 27.0f);
        float tx = __fdiv_rn((float)j, 27.0f);
        float ys = __fmul_rn(__fadd_rn(y1, __fmul_rn(ty, dy)), 159.0f);
        float xs = __fmul_rn(__fadd_rn(x1, __fmul_rn(tx, dx)), 159.0f);
        float y0f = floorf(ys), x0f = floorf(xs);
        float fy = __fsub_rn(ys, y0f), fx = __fsub_rn(xs, x0f);
        int y0 = min(max((int)y0f, 0), IH - 1);
        int x0 = min(max((int)x0f, 0), IW - 1);
        int y1i = min(y0 + 1, IH - 1);
        int x1i = min(x0 + 1, IW - 1);
        float m00 = img[((size_t)y0 * IW + x0) * NG];
        float m01 = img[((size_t)y0 * IW + x1i) * NG];
        float m10 = img[((size_t)y1i * IW + x0) * NG];
        float m11 = img[((size_t)y1i * IW + x1i) * NG];
        float ofy = __fsub_rn(1.0f, fy), ofx = __fsub_rn(1.0f, fx);
        float v = __fadd_rn(__fadd_rn(__fadd_rn(
                    __fmul_rn(__fmul_rn(m00, ofy), ofx),
                    __fmul_rn(__fmul_rn(m01, ofy), fx)),
                    __fmul_rn(__fmul_rn(m10, fy), ofx)),
                    __fmul_rn(__fmul_rn(m11, fy), fx));
        o[px] = rintf(v);
    }
}

extern "C" void kernel_launch(void* const* d_in, const int* in_sizes, int n_in,
                              void* d_out, int out_size) {
    const float* prop   = (const float*)d_in[0];
    const int*   gcls   = (const int*)d_in[1];
    const float* gbox   = (const float*)d_in[2];
    const float* pmasks = (const float*)d_in[3];
    const float* stdv   = (const float*)d_in[4];
    float* out = (float*)d_out;

    kA<<<NB, 256>>>(prop, gcls, gbox, stdv, out);
    kB<<<dim3(TR, NB), 128>>>(pmasks, out);
}

// round 10
// speedup vs baseline: 4.3899x; 2.9635x over previous
#include <cuda_runtime.h>
#include <stdint.h>

#define NB   16
#define NP   2000
#define NSORT 2048
#define NG   100
#define IH   160
#define IW   160
#define MHH  28
#define MWW  28
#define NPOS 66
#define NNEG 134
#define TR   200

#define ROIS_OFF 0
#define CLS_OFF  (NB*TR*4)            /* 12800 */
#define DLT_OFF  (CLS_OFF + NB*TR)    /* 16000 */
#define MSK_OFF  (DLT_OFF + NB*TR*4)  /* 28800 */

__device__ float g_pbox[NB*NPOS*4];
__device__ int   g_gidx[NB*NPOS];
__device__ int   g_pval[NB*NPOS];

__device__ unsigned long long g_keyp[NB*NSORT];
__device__ unsigned long long g_keyn[NB*NSORT];
__device__ int g_pselidx[NB*NPOS];
__device__ int g_pselval[NB*NPOS];
__device__ int g_nselidx[NB*NNEG];
__device__ int g_nselval[NB*NNEG];

// ---------------- Threefry-2x32 ----------------
__device__ __forceinline__ void tf(uint32_t k0, uint32_t k1, uint32_t& x0, uint32_t& x1) {
    uint32_t k2 = k0 ^ k1 ^ 0x1BD11BDAu;
    x0 += k0; x1 += k1;
#define RND(r) { x0 += x1; x1 = (x1 << (r)) | (x1 >> (32 - (r))); x1 ^= x0; }
    RND(13) RND(15) RND(26) RND(6)
    x0 += k1; x1 += k2 + 1u;
    RND(17) RND(29) RND(16) RND(24)
    x0 += k2; x1 += k0 + 2u;
    RND(13) RND(15) RND(26) RND(6)
    x0 += k0; x1 += k1 + 3u;
    RND(17) RND(29) RND(16) RND(24)
    x0 += k1; x1 += k2 + 4u;
    RND(13) RND(15) RND(26) RND(6)
    x0 += k2; x1 += k0 + 5u;
#undef RND
}

// jax.random.uniform(key,(2000,)) element p — threefry_partitionable=True path.
__device__ __forceinline__ float jax_unif(uint32_t k0, uint32_t k1, int p) {
    uint32_t x0 = 0u, x1 = (uint32_t)p;
    tf(k0, k1, x0, x1);
    uint32_t bits = x0 ^ x1;
    float f = __uint_as_float((bits >> 9) | 0x3F800000u) - 1.0f;
    return fmaxf(0.0f, f);
}

// Order-preserving float->uint32 map (total order, ascending).
__device__ __forceinline__ uint32_t ford(float f) {
    uint32_t b = __float_as_uint(f);
    return (b & 0x80000000u) ? ~b : (b | 0x80000000u);
}

// ---------------- IoU (unfused rounding to match XLA elementwise) ----------
__device__ __forceinline__ float iou_f(float4 p, float4 g) {
    float yA = fmaxf(p.x, g.x), xA = fmaxf(p.y, g.y);
    float yB = fminf(p.z, g.z), xB = fminf(p.w, g.w);
    float ih = fmaxf(__fsub_rn(yB, yA), 0.0f);
    float iw = fmaxf(__fsub_rn(xB, xA), 0.0f);
    float inter = __fmul_rn(ih, iw);
    float a1 = __fmul_rn(__fsub_rn(p.z, p.x), __fsub_rn(p.w, p.y));
    float a2 = __fmul_rn(__fsub_rn(g.z, g.x), __fsub_rn(g.w, g.y));
    float uni = __fsub_rn(__fadd_rn(a1, a2), inter);
    return __fdiv_rn(inter, fmaxf(uni, 1e-10f));
}

// ---------------- kScore: per-proposal max-IoU -> sort keys ----------------
__global__ __launch_bounds__(256) void kScore(const float* __restrict__ prop,
                                              const int*   __restrict__ gcls,
                                              const float* __restrict__ gbox) {
    const int b = blockIdx.y;
    const int tid = threadIdx.x;
    const int p = blockIdx.x * 256 + tid;    // 8*256 = 2048 covers NSORT

    __shared__ float4 s_gt[NG];
    __shared__ int    s_gtv[NG];
    __shared__ uint32_t s_keys[4];

    for (int g = tid; g < NG; g += 256) {
        const float* gp = gbox + ((size_t)b * NG + g) * 4;
        s_gt[g] = make_float4(gp[0], gp[1], gp[2], gp[3]);
        s_gtv[g] = (gcls[b * NG + g] > 0) ? 1 : 0;
    }
    if (tid == 0) {
        // keys[b] = TF((0,42),(0,b)); kp = TF(keys[b],(0,0)); kn = TF(keys[b],(0,1))
        uint32_t kb0 = 0u, kb1 = (uint32_t)b;
        tf(0u, 42u, kb0, kb1);
        uint32_t p0 = 0u, p1 = 0u; tf(kb0, kb1, p0, p1);
        uint32_t n0 = 0u, n1 = 1u; tf(kb0, kb1, n0, n1);
        s_keys[0] = p0; s_keys[1] = p1;
        s_keys[2] = n0; s_keys[3] = n1;
    }
    __syncthreads();

    if (p >= NSORT) return;
    unsigned long long keyp = 0ull, keyn = 0ull;
    if (p < NP) {
        float4 pb = ((const float4*)(prop + (size_t)b * NP * 4))[p];
        bool vp = (pb.x != 0.0f) || (pb.y != 0.0f) || (pb.z != 0.0f) || (pb.w != 0.0f);
        float m = -1.0f;
        #pragma unroll 4
        for (int g = 0; g < NG; g++) {
            float v = s_gtv[g] ? iou_f(pb, s_gt[g]) : -1.0f;
            m = fmaxf(m, v);
        }
        bool pos = (m >= 0.5f) && vp;
        bool neg = (m <  0.5f) && vp;
        float sp = pos ? jax_unif(s_keys[0], s_keys[1], p) : -1.0f;
        float sn = neg ? jax_unif(s_keys[2], s_keys[3], p) : -1.0f;
        uint32_t low = (uint32_t)(NP - 1 - p);
        keyp = ((unsigned long long)ford(sp) << 32) | low;
        keyn = ((unsigned long long)ford(sn) << 32) | low;
    }
    g_keyp[(size_t)b * NSORT + p] = keyp;
    g_keyn[(size_t)b * NSORT + p] = keyn;
}

// ---------------- kSort: descending bitonic sort (== lax.top_k order) ------
__global__ __launch_bounds__(1024) void kSort() {
    const int b = blockIdx.y;
    const bool dop = (blockIdx.x == 0);
    const int tid = threadIdx.x;

    __shared__ unsigned long long s_key[NSORT];
    const unsigned long long* src = (dop ? g_keyp : g_keyn) + (size_t)b * NSORT;
    for (int i = tid; i < NSORT; i += 1024) s_key[i] = src[i];

    for (unsigned k = 2; k <= NSORT; k <<= 1) {
        for (unsigned j = k >> 1; j > 0; j >>= 1) {
            __syncthreads();
            for (unsigned i = tid; i < NSORT; i += 1024) {
                unsigned ixj = i ^ j;
                if (ixj > i) {
                    unsigned long long a = s_key[i], c = s_key[ixj];
                    bool up = ((i & k) == 0);
                    if (up ? (a < c) : (a > c)) { s_key[i] = c; s_key[ixj] = a; }
                }
            }
        }
    }
    __syncthreads();

    if (dop) {
        if (tid < NPOS) {
            unsigned long long key = s_key[tid];
            g_pselval[b * NPOS + tid] = ((uint32_t)(key >> 32) > 0x80000000u) ? 1 : 0;
            g_pselidx[b * NPOS + tid] = NP - 1 - (int)(key & 0xFFFFFFFFu);
        }
    } else {
        if (tid < NNEG) {
            unsigned long long key = s_key[tid];
            g_nselval[b * NNEG + tid] = ((uint32_t)(key >> 32) > 0x80000000u) ? 1 : 0;
            g_nselidx[b * NNEG + tid] = NP - 1 - (int)(key & 0xFFFFFFFFu);
        }
    }
}

// ---------------- kEpi: rois / class / deltas + mask scratch ----------------
__global__ __launch_bounds__(256) void kEpi(const float* __restrict__ prop,
                                            const int*   __restrict__ gcls,
                                            const float* __restrict__ gbox,
                                            const float* __restrict__ stdv,
                                            float* __restrict__ out) {
    const int b = blockIdx.x;
    const int tid = threadIdx.x;

    __shared__ float4 s_gt[NG];
    __shared__ int    s_gtv[NG];
    __shared__ int    s_nn;

    for (int g = tid; g < NG; g += 256) {
        const float* gp = gbox + ((size_t)b * NG + g) * 4;
        s_gt[g] = make_float4(gp[0], gp[1], gp[2], gp[3]);
        s_gtv[g] = (gcls[b * NG + g] > 0) ? 1 : 0;
    }
    if (tid == 0) {
        int P = 0;
        for (int i = 0; i < NPOS; i++) P += g_pselval[b * NPOS + i];
        // XLA lowers x/0.33f to x * (1/0.33f): P=66 -> 200.0 -> nn=134.
        constexpr float RCP33 = 1.0f / 0.33f;
        int nn = (int)(__fmul_rn((float)P, RCP33)) - P;
        nn = max(0, min(nn, NNEG));
        s_nn = nn;
    }
    __syncthreads();

    const float4* pb4 = (const float4*)(prop + (size_t)b * NP * 4);
    const float sd0 = stdv[0], sd1 = stdv[1], sd2 = stdv[2], sd3 = stdv[3];

    for (int i = tid; i < NPOS; i += 256) {
        int idx = g_pselidx[b * NPOS + i];
        int valid = g_pselval[b * NPOS + i];
        float4 pb = pb4[idx];

        // argmax over masked overlaps (first max on ties)
        float bv = -2.0f; int bg = 0;
        for (int g = 0; g < NG; g++) {
            float v = s_gtv[g] ? iou_f(pb, s_gt[g]) : -1.0f;
            if (v > bv) { bv = v; bg = g; }
        }
        float4 gb = valid ? s_gt[bg] : pb;
        int cls = valid ? gcls[b * NG + bg] : 0;

        float h  = __fsub_rn(pb.z, pb.x), w  = __fsub_rn(pb.w, pb.y);
        float cy = __fadd_rn(pb.x, __fmul_rn(0.5f, h));
        float cx = __fadd_rn(pb.y, __fmul_rn(0.5f, w));
        float gh  = __fsub_rn(gb.z, gb.x), gw  = __fsub_rn(gb.w, gb.y);
        float gcy = __fadd_rn(gb.x, __fmul_rn(0.5f, gh));
        float gcx = __fadd_rn(gb.y, __fmul_rn(0.5f, gw));
        float d0 = __fdiv_rn(__fdiv_rn(__fsub_rn(gcy, cy), h), sd0);
        float d1 = __fdiv_rn(__fdiv_rn(__fsub_rn(gcx, cx), w), sd1);
        float d2 = __fdiv_rn(logf(__fdiv_rn(gh, h)), sd2);
        float d3 = __fdiv_rn(logf(__fdiv_rn(gw, w)), sd3);

        float fv = valid ? 1.0f : 0.0f;
        size_t ro = (size_t)ROIS_OFF + ((size_t)b * TR + i) * 4;
        out[ro + 0] = __fmul_rn(pb.x, fv);
        out[ro + 1] = __fmul_rn(pb.y, fv);
        out[ro + 2] = __fmul_rn(pb.z, fv);
        out[ro + 3] = __fmul_rn(pb.w, fv);
        out[CLS_OFF + (size_t)b * TR + i] = (float)cls;
        size_t dofs = (size_t)DLT_OFF + ((size_t)b * TR + i) * 4;
        out[dofs + 0] = __fmul_rn(d0, fv);
        out[dofs + 1] = __fmul_rn(d1, fv);
        out[dofs + 2] = __fmul_rn(d2, fv);
        out[dofs + 3] = __fmul_rn(d3, fv);

        int si = b * NPOS + i;
        g_pbox[si * 4 + 0] = pb.x; g_pbox[si * 4 + 1] = pb.y;
        g_pbox[si * 4 + 2] = pb.z; g_pbox[si * 4 + 3] = pb.w;
        g_gidx[si] = bg;
        g_pval[si] = valid;
    }

    for (int j = tid; j < NNEG; j += 256) {
        int slot = NPOS + j;
        int idx = g_nselidx[b * NNEG + j];
        float nv = (g_nselval[b * NNEG + j] && (j < s_nn)) ? 1.0f : 0.0f;
        float4 pb = pb4[idx];
        size_t ro = (size_t)ROIS_OFF + ((size_t)b * TR + slot) * 4;
        out[ro + 0] = __fmul_rn(pb.x, nv);
        out[ro + 1] = __fmul_rn(pb.y, nv);
        out[ro + 2] = __fmul_rn(pb.z, nv);
        out[ro + 3] = __fmul_rn(pb.w, nv);
        out[CLS_OFF + (size_t)b * TR + slot] = 0.0f;
        size_t dofs = (size_t)DLT_OFF + ((size_t)b * TR + slot) * 4;
        out[dofs + 0] = 0.0f; out[dofs + 1] = 0.0f;
        out[dofs + 2] = 0.0f; out[dofs + 3] = 0.0f;
    }
}

// ---------------- kB: mask crop_and_resize + round (smem-staged) -----------
#define RMAX 52
__global__ __launch_bounds__(128) void kB(const float* __restrict__ pmasks,
                                          float* __restrict__ out) {
    const int slot = blockIdx.x;
    const int b = blockIdx.y;
    float* o = out + (size_t)MSK_OFF + ((size_t)b * TR + slot) * (MHH * MWW);

    __shared__ float s_img[RMAX * RMAX];

    if (slot >= NPOS || !g_pval[b * NPOS + slot]) {
        for (int px = threadIdx.x; px < MHH * MWW; px += 128) o[px] = 0.0f;
        return;
    }
    const int si = b * NPOS + slot;
    const float y1 = g_pbox[si * 4 + 0], x1 = g_pbox[si * 4 + 1];
    const float y2 = g_pbox[si * 4 + 2], x2 = g_pbox[si * 4 + 3];
    const int g = g_gidx[si];
    const float* img = pmasks + (size_t)b * (IH * IW * NG) + g;
    const float dy = __fsub_rn(y2, y1), dx = __fsub_rn(x2, x1);

    // staging region (covers all clamped bilinear taps; +1 margin for safety)
    int ylo = min(max((int)floorf(__fmul_rn(y1, 159.0f)), 0), IH - 1);
    int xlo = min(max((int)floorf(__fmul_rn(x1, 159.0f)), 0), IW - 1);
    int yhi = min((int)floorf(__fmul_rn(__fadd_rn(y1, dy), 159.0f)) + 2, IH - 1);
    int xhi = min((int)floorf(__fmul_rn(__fadd_rn(x1, dx), 159.0f)) + 2, IW - 1);
    int rows = yhi - ylo + 1, cols = xhi - xlo + 1;
    bool staged = (rows <= RMAX) && (cols <= RMAX);

    if (staged) {
        for (int idx = threadIdx.x; idx < rows * cols; idx += 128) {
            int r = idx / cols, c = idx - r * cols;
            s_img[idx] = img[((size_t)(ylo + r) * IW + (xlo + c)) * NG];
        }
        __syncthreads();
    }

    for (int px = threadIdx.x; px < MHH * MWW; px += 128) {
        int i = px / MWW, j = px - i * MWW;
        float ty = __fdiv_rn((float)i, 27.0f);
        float tx = __fdiv_rn((float)j, 27.0f);
        float ys = __fmul_rn(__fadd_rn(y1, __fmul_rn(ty, dy)), 159.0f);
        float xs = __fmul_rn(__fadd_rn(x1, __fmul_rn(tx, dx)), 159.0f);
        float y0f = floorf(ys), x0f = floorf(xs);
        float fy = __fsub_rn(ys, y0f), fx = __fsub_rn(xs, x0f);
        int y0 = min(max((int)y0f, 0), IH - 1);
        int x0 = min(max((int)x0f, 0), IW - 1);
        int y1i = min(y0 + 1, IH - 1);
        int x1i = min(x0 + 1, IW - 1);
        float m00, m01, m10, m11;
        if (staged && y0 >= ylo && y1i <= yhi && x0 >= xlo && x1i <= xhi) {
            int ly0 = y0 - ylo, ly1 = y1i - ylo, lx0 = x0 - xlo, lx1 = x1i - xlo;
            m00 = s_img[ly0 * cols + lx0];
            m01 = s_img[ly0 * cols + lx1];
            m10 = s_img[ly1 * cols + lx0];
            m11 = s_img[ly1 * cols + lx1];
        } else {
            m00 = img[((size_t)y0 * IW + x0) * NG];
            m01 = img[((size_t)y0 * IW + x1i) * NG];
            m10 = img[((size_t)y1i * IW + x0) * NG];
            m11 = img[((size_t)y1i * IW + x1i) * NG];
        }
        float ofy = __fsub_rn(1.0f, fy), ofx = __fsub_rn(1.0f, fx);
        float v = __fadd_rn(__fadd_rn(__fadd_rn(
                    __fmul_rn(__fmul_rn(m00, ofy), ofx),
                    __fmul_rn(__fmul_rn(m01, ofy), fx)),
                    __fmul_rn(__fmul_rn(m10, fy), ofx)),
                    __fmul_rn(__fmul_rn(m11, fy), fx));
        o[px] = rintf(v);
    }
}

extern "C" void kernel_launch(void* const* d_in, const int* in_sizes, int n_in,
                              void* d_out, int out_size) {
    const float* prop   = (const float*)d_in[0];
    const int*   gcls   = (const int*)d_in[1];
    const float* gbox   = (const float*)d_in[2];
    const float* pmasks = (const float*)d_in[3];
    const float* stdv   = (const float*)d_in[4];
    float* out = (float*)d_out;

    kScore<<<dim3(8, NB), 256>>>(prop, gcls, gbox);
    kSort<<<dim3(2, NB), 1024>>>();
    kEpi<<<NB, 256>>>(prop, gcls, gbox, stdv, out);
    kB<<<dim3(TR, NB), 128>>>(pmasks, out);
}